// round 13
// baseline (speedup 1.0000x reference)
#include <cuda_runtime.h>
#include <cuda_bf16.h>
#include <cstdint>

#define BB 16
#define MM 128
#define NH 256
#define EH 128
#define RR (BB*MM)          // 2048

typedef __nv_bfloat16 bf16;

// ---------------- scratch (all L2-resident) ----------------
__device__ __align__(128) float g_sA [RR];
__device__ __align__(128) float g_pO [3][RR * NH];
__device__ __align__(128) bf16 g_Xh [RR*NH],  g_Xl [RR*NH];
__device__ __align__(128) bf16 g_Xrh[RR*NH],  g_Xrl[RR*NH];
__device__ __align__(128) bf16 g_WvTh[NH*NH], g_WvTl[NH*NH];      // Wv^T [n][k]
__device__ __align__(128) bf16 g_WeTh[EH*EH], g_WeTl[EH*EH];      // We^T
__device__ __align__(128) bf16 g_WuTh[NH*640],g_WuTl[NH*640];     // Wu^T [n][k=640]
__device__ __align__(128) bf16 g_ATh[BB*MM*MM], g_ATl[BB*MM*MM];  // A^T [b][j][i]
__device__ __align__(128) bf16 g_NMTh[BB*NH*MM],g_NMTl[BB*NH*MM]; // nodeMap^T [b][n][i]
__device__ __align__(128) bf16 g_hNh[RR*NH],  g_hNl[RR*NH];
__device__ __align__(128) bf16 g_aEh[RR*EH],  g_aEl[RR*EH];
__device__ __align__(128) bf16 g_hEh[RR*EH],  g_hEl[RR*EH];

__device__ __forceinline__ void bsplit(float v, bf16& h, bf16& l) {
    h = __float2bfloat16(v);
    l = __float2bfloat16(v - __bfloat162float(h));
}

// ---------------- PTX helpers (compute_103-legal) ----------------
__device__ __forceinline__ uint32_t smem_u32(const void* p) {
    uint32_t a;
    asm("{ .reg .u64 t; cvta.to.shared.u64 t, %1; cvt.u32.u64 %0, t; }" : "=r"(a) : "l"(p));
    return a;
}
__device__ __forceinline__ void cpa16(uint32_t dst, const void* src) {
    asm volatile("cp.async.cg.shared.global [%0], [%1], 16;" :: "r"(dst), "l"(src));
}
__device__ __forceinline__ void ldsm4(uint32_t* r, uint32_t a) {
    asm volatile("ldmatrix.sync.aligned.m8n8.x4.shared.b16 {%0,%1,%2,%3}, [%4];"
                 : "=r"(r[0]), "=r"(r[1]), "=r"(r[2]), "=r"(r[3]) : "r"(a));
}
__device__ __forceinline__ void ldsm2(uint32_t* r, uint32_t a) {
    asm volatile("ldmatrix.sync.aligned.m8n8.x2.shared.b16 {%0,%1}, [%2];"
                 : "=r"(r[0]), "=r"(r[1]) : "r"(a));
}
__device__ __forceinline__ void mma16816(float* c, const uint32_t* a, const uint32_t* b) {
    asm volatile(
        "mma.sync.aligned.m16n8k16.row.col.f32.bf16.bf16.f32 "
        "{%0,%1,%2,%3}, {%4,%5,%6,%7}, {%8,%9}, {%0,%1,%2,%3};"
        : "+f"(c[0]), "+f"(c[1]), "+f"(c[2]), "+f"(c[3])
        : "r"(a[0]), "r"(a[1]), "r"(a[2]), "r"(a[3]), "r"(b[0]), "r"(b[1]));
}

// ============================================================================
// Shared MMA core: computes acc[2][4][4] for a 64x64 tile, split-bf16 x3.
// ============================================================================
template <int KDIM>
struct MmaCore {
    __device__ static void run(
        float acc[2][4][4],
        const bf16* gA0, const bf16* gA1, int lda,
        const bf16* gB0, const bf16* gB1, int ldb,
        int rowBase, int colBase, int kbOff,
        bf16 (*sAh)[64][40], bf16 (*sAl)[64][40],
        bf16 (*sBh)[64][40], bf16 (*sBl)[64][40],
        int tid)
    {
        int lane = tid & 31, wid = tid >> 5;
        int wm = (wid & 1) * 32, wn = (wid >> 1) * 32;
        int ldRow = tid >> 1;
        int ldSeg = (tid & 1) * 16;

        auto loadStage = [&](int kt, int buf) {
            int k0 = kt * 32;
            const bf16* a0 = gA0 + (size_t)(rowBase + ldRow) * lda + k0 + ldSeg;
            const bf16* a1 = gA1 + (size_t)(rowBase + ldRow) * lda + k0 + ldSeg;
            const bf16* b0 = gB0 + (size_t)(colBase + ldRow) * ldb + kbOff + k0 + ldSeg;
            const bf16* b1 = gB1 + (size_t)(colBase + ldRow) * ldb + kbOff + k0 + ldSeg;
            uint32_t dA0 = smem_u32(&sAh[buf][ldRow][ldSeg]);
            uint32_t dA1 = smem_u32(&sAl[buf][ldRow][ldSeg]);
            uint32_t dB0 = smem_u32(&sBh[buf][ldRow][ldSeg]);
            uint32_t dB1 = smem_u32(&sBl[buf][ldRow][ldSeg]);
            cpa16(dA0, a0); cpa16(dA0 + 16, a0 + 8);
            cpa16(dA1, a1); cpa16(dA1 + 16, a1 + 8);
            cpa16(dB0, b0); cpa16(dB0 + 16, b0 + 8);
            cpa16(dB1, b1); cpa16(dB1 + 16, b1 + 8);
        };

        const int NT = KDIM / 32;
        loadStage(0, 0);
        asm volatile("cp.async.commit_group;" ::: "memory");

        int aRow = lane & 15, aSel = (lane >> 4) * 8;
        int bRow = lane & 7,  bSel = ((lane >> 3) & 1) * 8;

        for (int t = 0; t < NT; t++) {
            int cur = t & 1;
            if (t + 1 < NT) {
                loadStage(t + 1, (t + 1) & 1);
                asm volatile("cp.async.commit_group;" ::: "memory");
                asm volatile("cp.async.wait_group 1;" ::: "memory");
            } else {
                asm volatile("cp.async.wait_group 0;" ::: "memory");
            }
            __syncthreads();

#pragma unroll
            for (int kk = 0; kk < 32; kk += 16) {
                uint32_t Afh[2][4], Afl[2][4], Bfh[4][2], Bfl[4][2];
#pragma unroll
                for (int mi = 0; mi < 2; mi++) {
                    ldsm4(Afh[mi], smem_u32(&sAh[cur][wm + mi * 16 + aRow][kk + aSel]));
                    ldsm4(Afl[mi], smem_u32(&sAl[cur][wm + mi * 16 + aRow][kk + aSel]));
                }
#pragma unroll
                for (int ni = 0; ni < 4; ni++) {
                    ldsm2(Bfh[ni], smem_u32(&sBh[cur][wn + ni * 8 + bRow][kk + bSel]));
                    ldsm2(Bfl[ni], smem_u32(&sBl[cur][wn + ni * 8 + bRow][kk + bSel]));
                }
#pragma unroll
                for (int mi = 0; mi < 2; mi++)
#pragma unroll
                    for (int ni = 0; ni < 4; ni++) {
                        mma16816(acc[mi][ni], Afh[mi], Bfh[ni]);
                        mma16816(acc[mi][ni], Afh[mi], Bfl[ni]);
                        mma16816(acc[mi][ni], Afl[mi], Bfh[ni]);
                    }
            }
            __syncthreads();
        }
    }
};

// ---------------------------------------------------------------------------
// Generic GEMM (as R12): EMODE 0 fp32 / 2 relu-split / 3 relu+sA*b split
// ---------------------------------------------------------------------------
template <int KDIM, int EMODE>
__global__ __launch_bounds__(128) void tmm(
    const bf16* __restrict__ Ah, const bf16* __restrict__ Al, int lda, size_t aStr,
    const bf16* __restrict__ Bh, const bf16* __restrict__ Bl, int ldb, int kbOff, size_t bStr,
    const float* __restrict__ sAv, const float* __restrict__ eb,
    float* __restrict__ Pf, bf16* __restrict__ Ph, bf16* __restrict__ Pl,
    int ldp, size_t pStr)
{
    __shared__ bf16 sAh[2][64][40], sAl[2][64][40], sBh[2][64][40], sBl[2][64][40];
    int tid = threadIdx.x;
    int lane = tid & 31, wid = tid >> 5;
    int wm = (wid & 1) * 32, wn = (wid >> 1) * 32;
    int rowBase = blockIdx.x * 64, colBase = blockIdx.y * 64;
    int z = blockIdx.z;

    float acc[2][4][4] = {};
    MmaCore<KDIM>::run(acc, Ah + (size_t)z * aStr, Al + (size_t)z * aStr, lda,
                       Bh + (size_t)z * bStr, Bl + (size_t)z * bStr, ldb,
                       rowBase, colBase, kbOff, sAh, sAl, sBh, sBl, tid);

    int t4 = lane >> 2, t2 = (lane & 3) * 2;
#pragma unroll
    for (int mi = 0; mi < 2; mi++)
#pragma unroll
        for (int half = 0; half < 2; half++) {
            int lr = wm + mi * 16 + t4 + half * 8;
            int grow = rowBase + lr;
#pragma unroll
            for (int ni = 0; ni < 4; ni++) {
                float v0 = acc[mi][ni][half * 2 + 0];
                float v1 = acc[mi][ni][half * 2 + 1];
                int c0 = colBase + wn + ni * 8 + t2;
                if (EMODE == 0) {
                    float* po = Pf + (size_t)z * pStr + (size_t)grow * ldp;
                    po[c0] = v0; po[c0 + 1] = v1;
                } else {
                    float w0 = v0, w1 = v1;
                    if (EMODE == 3) {
                        float sa = sAv[grow];
                        w0 += sa * eb[c0]; w1 += sa * eb[c0 + 1];
                    }
                    w0 = fmaxf(w0, 0.f); w1 = fmaxf(w1, 0.f);
                    bf16* ph = Ph + (size_t)z * pStr + (size_t)grow * ldp;
                    bf16* pl = Pl + (size_t)z * pStr + (size_t)grow * ldp;
                    bf16 h, l;
                    bsplit(w0, h, l); ph[c0] = h; pl[c0] = l;
                    bsplit(w1, h, l); ph[c0 + 1] = h; pl[c0 + 1] = l;
                }
            }
        }
}

// ---------------------------------------------------------------------------
// k_dual: z=0 -> NM^T = (X@Wv + Wv_b)^T (transposed split store)
//         z=1 -> pO[1] = relu(X)@Wu[384:640] (fp32 store)
// Both: M=2048, N=256, K=256. grid (32,4,2).
// ---------------------------------------------------------------------------
__global__ __launch_bounds__(128) void k_dual(const float* __restrict__ Wv_b) {
    __shared__ bf16 sAh[2][64][40], sAl[2][64][40], sBh[2][64][40], sBl[2][64][40];
    int tid = threadIdx.x;
    int lane = tid & 31, wid = tid >> 5;
    int wm = (wid & 1) * 32, wn = (wid >> 1) * 32;
    int rowBase = blockIdx.x * 64, colBase = blockIdx.y * 64;
    int z = blockIdx.z;

    const bf16 *gA0, *gA1, *gB0, *gB1;
    int ldb, kbOff;
    if (z == 0) { gA0 = g_Xh;  gA1 = g_Xl;  gB0 = g_WvTh; gB1 = g_WvTl; ldb = NH;  kbOff = 0; }
    else        { gA0 = g_Xrh; gA1 = g_Xrl; gB0 = g_WuTh; gB1 = g_WuTl; ldb = 640; kbOff = 384; }

    float acc[2][4][4] = {};
    MmaCore<256>::run(acc, gA0, gA1, NH, gB0, gB1, ldb,
                      rowBase, colBase, kbOff, sAh, sAl, sBh, sBl, tid);

    int t4 = lane >> 2, t2 = (lane & 3) * 2;
#pragma unroll
    for (int mi = 0; mi < 2; mi++)
#pragma unroll
        for (int half = 0; half < 2; half++) {
            int lr = wm + mi * 16 + t4 + half * 8;
            int grow = rowBase + lr;
#pragma unroll
            for (int ni = 0; ni < 4; ni++) {
                float v0 = acc[mi][ni][half * 2 + 0];
                float v1 = acc[mi][ni][half * 2 + 1];
                int c0 = colBase + wn + ni * 8 + t2;
                if (z == 1) {
                    float* po = g_pO[1] + (size_t)grow * NH;
                    po[c0] = v0; po[c0 + 1] = v1;
                } else {
                    int b = grow >> 7, ml = grow & 127;
                    bf16* ph = g_NMTh + (size_t)b * (NH * MM);
                    bf16* pl = g_NMTl + (size_t)b * (NH * MM);
                    float w0 = v0 + Wv_b[c0], w1 = v1 + Wv_b[c0 + 1];
                    bf16 h, l;
                    bsplit(w0, h, l); ph[(size_t)c0 * MM + ml] = h; pl[(size_t)c0 * MM + ml] = l;
                    bsplit(w1, h, l); ph[(size_t)(c0 + 1) * MM + ml] = h; pl[(size_t)(c0 + 1) * MM + ml] = l;
                }
            }
        }
}

// ---------------------------------------------------------------------------
// k_prepX: vectorized X splits (X and relu(X)), grid 512 x 256, 4 elems/thread
// ---------------------------------------------------------------------------
__global__ __launch_bounds__(256) void k_prepX(const float* __restrict__ X) {
    int i4 = (blockIdx.x * 256 + threadIdx.x) * 4;
    float4 f = *(const float4*)(X + i4);
    bf16 h, l;
    bsplit(f.x, h, l); g_Xh[i4+0] = h; g_Xl[i4+0] = l;
    bsplit(f.y, h, l); g_Xh[i4+1] = h; g_Xl[i4+1] = l;
    bsplit(f.z, h, l); g_Xh[i4+2] = h; g_Xl[i4+2] = l;
    bsplit(f.w, h, l); g_Xh[i4+3] = h; g_Xl[i4+3] = l;
    bsplit(fmaxf(f.x, 0.f), h, l); g_Xrh[i4+0] = h; g_Xrl[i4+0] = l;
    bsplit(fmaxf(f.y, 0.f), h, l); g_Xrh[i4+1] = h; g_Xrl[i4+1] = l;
    bsplit(fmaxf(f.z, 0.f), h, l); g_Xrh[i4+2] = h; g_Xrl[i4+2] = l;
    bsplit(fmaxf(f.w, 0.f), h, l); g_Xrh[i4+3] = h; g_Xrl[i4+3] = l;
}

// ---------------------------------------------------------------------------
// k_prepT: ALL transpose+splits in one launch. 496 blocks of (32,32):
//   [0,256):  A^T per batch   (16 b x 4 kx x 4 ny)
//   [256,320): Wv^T           (8 kx x 8 ny)
//   [320,480): Wu^T           (20 kx x 8 ny)
//   [480,496): We^T           (4 kx x 4 ny)
// transpose semantics: in [K][N] row-major -> out[n][k]
// ---------------------------------------------------------------------------
__global__ void k_prepT(const float* __restrict__ A, const float* __restrict__ Wv,
                        const float* __restrict__ Wu, const float* __restrict__ We) {
    __shared__ float t[32][33];
    int id = blockIdx.x;
    const float* in; bf16 *Th, *Tl;
    int K, N, k0, n0;
    if (id < 256) {
        int b = id >> 4, r = id & 15;
        in = A + (size_t)b * MM * MM;
        Th = g_ATh + (size_t)b * MM * MM;
        Tl = g_ATl + (size_t)b * MM * MM;
        K = MM; N = MM; k0 = (r & 3) * 32; n0 = (r >> 2) * 32;
    } else if (id < 320) {
        int r = id - 256;
        in = Wv; Th = g_WvTh; Tl = g_WvTl;
        K = NH; N = NH; k0 = (r & 7) * 32; n0 = (r >> 3) * 32;
    } else if (id < 480) {
        int r = id - 320;
        in = Wu; Th = g_WuTh; Tl = g_WuTl;
        K = 640; N = NH; k0 = (r % 20) * 32; n0 = (r / 20) * 32;
    } else {
        int r = id - 480;
        in = We; Th = g_WeTh; Tl = g_WeTl;
        K = EH; N = EH; k0 = (r & 3) * 32; n0 = (r >> 2) * 32;
    }
    int tx = threadIdx.x, ty = threadIdx.y;
    t[ty][tx] = in[(size_t)(k0 + ty) * N + n0 + tx];
    __syncthreads();
    float v = t[tx][ty];
    bf16 h, l; bsplit(v, h, l);
    size_t o = (size_t)(n0 + ty) * K + k0 + tx;
    Th[o] = h; Tl[o] = l;
}

// ---------------------------------------------------------------------------
// Persistent E reduction -> split bf16 aggE + sA (512 CTAs grid-stride)
// ---------------------------------------------------------------------------
__global__ __launch_bounds__(256) void k_agge(const float* __restrict__ A,
                                              const float* __restrict__ E) {
    __shared__ float Ac[MM];
    __shared__ float red[8][EH];
    int t = threadIdx.x;
    int lane = t & 31, grp = t >> 5;

    for (int r = blockIdx.x; r < RR; r += gridDim.x) {
        int b = r >> 7, j = r & 127;
        if (t < MM) Ac[t] = A[(b * MM + t) * MM + j];
        __syncthreads();

        const float* Eb = E + ((size_t)b * MM * MM + j) * EH;
        float4 acc = {0.f, 0.f, 0.f, 0.f};
#pragma unroll
        for (int ii = 0; ii < MM; ii += 16) {
            int i0 = ii + grp, i1 = ii + 8 + grp;
            float4 v0 = *(const float4*)(Eb + (size_t)i0 * MM * EH + lane * 4);
            float4 v1 = *(const float4*)(Eb + (size_t)i1 * MM * EH + lane * 4);
            float a0 = Ac[i0], a1 = Ac[i1];
            acc.x += a0 * v0.x + a1 * v1.x;
            acc.y += a0 * v0.y + a1 * v1.y;
            acc.z += a0 * v0.z + a1 * v1.z;
            acc.w += a0 * v0.w + a1 * v1.w;
        }
        *(float4*)&red[grp][lane * 4] = acc;
        __syncthreads();
        if (t < EH) {
            float s = 0.f;
#pragma unroll
            for (int g = 0; g < 8; g++) s += red[g][t];
            bf16 h, l; bsplit(s, h, l);
            g_aEh[(size_t)r * EH + t] = h;
            g_aEl[(size_t)r * EH + t] = l;
        }
        if (t == 0) {
            float s = 0.f;
#pragma unroll
            for (int i = 0; i < MM; i++) s += Ac[i];
            g_sA[r] = s;
        }
        __syncthreads();
    }
}

// ---------------------------------------------------------------------------
__global__ __launch_bounds__(256) void k_final(const float* __restrict__ Wub,
                                               const float* __restrict__ w,
                                               float* __restrict__ out) {
    int r = blockIdx.x, n = threadIdx.x;
    size_t idx = (size_t)r * NH + n;
    float s = g_pO[0][idx] + g_pO[1][idx] + g_pO[2][idx];
    out[idx] = (s + Wub[n]) * w[r];
}

// ---------------------------------------------------------------------------
extern "C" void kernel_launch(void* const* d_in, const int* in_sizes, int n_in,
                              void* d_out, int out_size) {
    const float* X    = (const float*)d_in[0];
    const float* E    = (const float*)d_in[1];
    const float* A    = (const float*)d_in[2];
    const float* w    = (const float*)d_in[3];
    const float* Wv_w = (const float*)d_in[4];
    const float* Wv_b = (const float*)d_in[5];
    const float* We_w = (const float*)d_in[6];
    const float* We_b = (const float*)d_in[7];
    const float* Wu_w = (const float*)d_in[8];
    const float* Wu_b = (const float*)d_in[9];
    float* out = (float*)d_out;

    float *pO, *psA;
    cudaGetSymbolAddress((void**)&pO,  g_pO);
    cudaGetSymbolAddress((void**)&psA, g_sA);
    bf16 *WeTh,*WeTl,*WuTh,*WuTl,*ATh,*ATl,*NMTh,*NMTl,*hNh,*hNl,*aEh,*aEl,*hEh,*hEl;
    cudaGetSymbolAddress((void**)&WeTh,g_WeTh); cudaGetSymbolAddress((void**)&WeTl,g_WeTl);
    cudaGetSymbolAddress((void**)&WuTh,g_WuTh); cudaGetSymbolAddress((void**)&WuTl,g_WuTl);
    cudaGetSymbolAddress((void**)&ATh, g_ATh);  cudaGetSymbolAddress((void**)&ATl, g_ATl);
    cudaGetSymbolAddress((void**)&NMTh,g_NMTh); cudaGetSymbolAddress((void**)&NMTl,g_NMTl);
    cudaGetSymbolAddress((void**)&hNh, g_hNh);  cudaGetSymbolAddress((void**)&hNl, g_hNl);
    cudaGetSymbolAddress((void**)&aEh, g_aEh);  cudaGetSymbolAddress((void**)&aEl, g_aEl);
    cudaGetSymbolAddress((void**)&hEh, g_hEh);  cudaGetSymbolAddress((void**)&hEl, g_hEl);
    const size_t SL = (size_t)RR * NH;

    cudaStream_t sB, sC;
    cudaStreamCreateWithFlags(&sB, cudaStreamNonBlocking);
    cudaStreamCreateWithFlags(&sC, cudaStreamNonBlocking);
    cudaEvent_t e0, eT, eB;
    cudaEventCreateWithFlags(&e0, cudaEventDisableTiming);
    cudaEventCreateWithFlags(&eT, cudaEventDisableTiming);
    cudaEventCreateWithFlags(&eB, cudaEventDisableTiming);

    cudaEventRecord(e0, 0);
    cudaStreamWaitEvent(sB, e0, 0);
    cudaStreamWaitEvent(sC, e0, 0);

    // ---- sB: E reduction (DRAM-bound, starts immediately) ----
    k_agge<<<512, 256, 0, sB>>>(A, E);

    // ---- sC: all transposes+splits in one kernel ----
    k_prepT<<<496, dim3(32, 32), 0, sC>>>(A, Wv_w, Wu_w, We_w);
    cudaEventRecord(eT, sC);

    // ---- s0: X split -> dual GEMM -> node chain ----
    k_prepX<<<512, 256>>>(X);
    cudaStreamWaitEvent(0, eT, 0);
    // z=0: NM^T = (X@Wv+b)^T ; z=1: pO[1] = relu(X)@Wu[384:640]
    k_dual<<<dim3(32, 4, 2), 128>>>(Wv_b);
    // hN = relu(A^T @ NM) per batch
    tmm<128, 2><<<dim3(2, 4, 16), 128>>>(
        ATh, ATl, MM, (size_t)MM * MM, NMTh, NMTl, MM, 0, (size_t)NH * MM,
        nullptr, nullptr, nullptr, hNh, hNl, NH, (size_t)MM * NH);
    // pO[0] = hN @ Wu[0:256]
    tmm<256, 0><<<dim3(32, 4, 1), 128>>>(
        hNh, hNl, NH, 0, WuTh, WuTl, 640, 0, 0,
        nullptr, nullptr, pO, nullptr, nullptr, NH, 0);

    // ---- sB: edge chain (after agge; needs We^T/Wu^T from eT) ----
    cudaStreamWaitEvent(sB, eT, 0);
    // hE = relu(aggE @ We + sA*We_b)
    tmm<128, 3><<<dim3(32, 2, 1), 128, 0, sB>>>(
        aEh, aEl, EH, 0, WeTh, WeTl, EH, 0, 0,
        psA, We_b, nullptr, hEh, hEl, EH, 0);
    // pO[2] = hE @ Wu[256:384]
    tmm<128, 0><<<dim3(32, 4, 1), 128, 0, sB>>>(
        hEh, hEl, EH, 0, WuTh, WuTl, 640, 256, 0,
        nullptr, nullptr, pO + 2 * SL, nullptr, nullptr, NH, 0);
    cudaEventRecord(eB, sB);

    // ---- join ----
    cudaStreamWaitEvent(0, eB, 0);
    k_final<<<RR, 256>>>(Wu_b, w, out);

    cudaEventDestroy(e0); cudaEventDestroy(eT); cudaEventDestroy(eB);
    cudaStreamDestroy(sB); cudaStreamDestroy(sC);
}

// round 14
// speedup vs baseline: 1.2381x; 1.2381x over previous
#include <cuda_runtime.h>
#include <cuda_bf16.h>
#include <cstdint>

#define BB 16
#define MM 128
#define NH 256
#define EH 128
#define RR (BB*MM)          // 2048

typedef __nv_bfloat16 bf16;

// ---------------- scratch (all L2-resident) ----------------
__device__ __align__(128) float g_sA [RR];
__device__ __align__(128) float g_pO [5][RR * NH];   // 0,1=hN halves  2,3=X halves  4=hE
__device__ __align__(128) bf16 g_Xh [RR*NH],  g_Xl [RR*NH];
__device__ __align__(128) bf16 g_Xrh[RR*NH],  g_Xrl[RR*NH];
__device__ __align__(128) bf16 g_WvTh[NH*NH], g_WvTl[NH*NH];      // Wv^T [n][k]
__device__ __align__(128) bf16 g_WeTh[EH*EH], g_WeTl[EH*EH];      // We^T
__device__ __align__(128) bf16 g_WuTh[NH*640],g_WuTl[NH*640];     // Wu^T [n][k=640]
__device__ __align__(128) bf16 g_ATh[BB*MM*MM], g_ATl[BB*MM*MM];  // A^T [b][j][i]
__device__ __align__(128) bf16 g_NMTh[BB*NH*MM],g_NMTl[BB*NH*MM]; // nodeMap^T [b][n][i]
__device__ __align__(128) bf16 g_hNh[RR*NH],  g_hNl[RR*NH];
__device__ __align__(128) bf16 g_aEh[RR*EH],  g_aEl[RR*EH];
__device__ __align__(128) bf16 g_hEh[RR*EH],  g_hEl[RR*EH];

__device__ __forceinline__ void bsplit(float v, bf16& h, bf16& l) {
    h = __float2bfloat16(v);
    l = __float2bfloat16(v - __bfloat162float(h));
}

// ---------------- PTX helpers (compute_103-legal) ----------------
__device__ __forceinline__ uint32_t smem_u32(const void* p) {
    uint32_t a;
    asm("{ .reg .u64 t; cvta.to.shared.u64 t, %1; cvt.u32.u64 %0, t; }" : "=r"(a) : "l"(p));
    return a;
}
__device__ __forceinline__ void cpa16(uint32_t dst, const void* src) {
    asm volatile("cp.async.cg.shared.global [%0], [%1], 16;" :: "r"(dst), "l"(src));
}
__device__ __forceinline__ void ldsm4(uint32_t* r, uint32_t a) {
    asm volatile("ldmatrix.sync.aligned.m8n8.x4.shared.b16 {%0,%1,%2,%3}, [%4];"
                 : "=r"(r[0]), "=r"(r[1]), "=r"(r[2]), "=r"(r[3]) : "r"(a));
}
__device__ __forceinline__ void ldsm2(uint32_t* r, uint32_t a) {
    asm volatile("ldmatrix.sync.aligned.m8n8.x2.shared.b16 {%0,%1}, [%2];"
                 : "=r"(r[0]), "=r"(r[1]) : "r"(a));
}
__device__ __forceinline__ void mma16816(float* c, const uint32_t* a, const uint32_t* b) {
    asm volatile(
        "mma.sync.aligned.m16n8k16.row.col.f32.bf16.bf16.f32 "
        "{%0,%1,%2,%3}, {%4,%5,%6,%7}, {%8,%9}, {%0,%1,%2,%3};"
        : "+f"(c[0]), "+f"(c[1]), "+f"(c[2]), "+f"(c[3])
        : "r"(a[0]), "r"(a[1]), "r"(a[2]), "r"(a[3]), "r"(b[0]), "r"(b[1]));
}

// ============================================================================
// MMA core, 256 threads (8 warps, warp grid 2Mx4N, warp tile 32x16).
// Computes/accumulates acc[2][2][4] over K=128 (4 stages of BK=32).
// Fragment mappings identical to the R12-verified 4-warp kernel.
// ============================================================================
__device__ __forceinline__ void mma_core_k128(
    float acc[2][2][4],
    const bf16* gA0, const bf16* gA1, int lda,
    const bf16* gB0, const bf16* gB1, int ldb, int kbOff,
    bf16 (*sAh)[64][40], bf16 (*sAl)[64][40],
    bf16 (*sBh)[64][40], bf16 (*sBl)[64][40],
    int rowBase, int colBase, int tid)
{
    int lane = tid & 31, wid = tid >> 5;
    int wm = (wid & 1) * 32, wn = (wid >> 1) * 16;
    int ldRow = tid >> 2;            // 0..63
    int ldSeg = (tid & 3) * 8;       // 0,8,16,24 bf16

    auto loadStage = [&](int kt, int buf) {
        int k0 = kt * 32;
        const bf16* a0 = gA0 + (size_t)(rowBase + ldRow) * lda + k0 + ldSeg;
        const bf16* a1 = gA1 + (size_t)(rowBase + ldRow) * lda + k0 + ldSeg;
        const bf16* b0 = gB0 + (size_t)(colBase + ldRow) * ldb + kbOff + k0 + ldSeg;
        const bf16* b1 = gB1 + (size_t)(colBase + ldRow) * ldb + kbOff + k0 + ldSeg;
        cpa16(smem_u32(&sAh[buf][ldRow][ldSeg]), a0);
        cpa16(smem_u32(&sAl[buf][ldRow][ldSeg]), a1);
        cpa16(smem_u32(&sBh[buf][ldRow][ldSeg]), b0);
        cpa16(smem_u32(&sBl[buf][ldRow][ldSeg]), b1);
    };

    loadStage(0, 0);
    asm volatile("cp.async.commit_group;" ::: "memory");

    int aRow = lane & 15, aSel = (lane >> 4) * 8;
    int bRow = lane & 7,  bSel = ((lane >> 3) & 1) * 8;

    for (int t = 0; t < 4; t++) {
        int cur = t & 1;
        if (t + 1 < 4) {
            loadStage(t + 1, (t + 1) & 1);
            asm volatile("cp.async.commit_group;" ::: "memory");
            asm volatile("cp.async.wait_group 1;" ::: "memory");
        } else {
            asm volatile("cp.async.wait_group 0;" ::: "memory");
        }
        __syncthreads();

#pragma unroll
        for (int kk = 0; kk < 32; kk += 16) {
            uint32_t Afh[2][4], Afl[2][4], Bfh[2][2], Bfl[2][2];
#pragma unroll
            for (int mi = 0; mi < 2; mi++) {
                ldsm4(Afh[mi], smem_u32(&sAh[cur][wm + mi * 16 + aRow][kk + aSel]));
                ldsm4(Afl[mi], smem_u32(&sAl[cur][wm + mi * 16 + aRow][kk + aSel]));
            }
#pragma unroll
            for (int ni = 0; ni < 2; ni++) {
                ldsm2(Bfh[ni], smem_u32(&sBh[cur][wn + ni * 8 + bRow][kk + bSel]));
                ldsm2(Bfl[ni], smem_u32(&sBl[cur][wn + ni * 8 + bRow][kk + bSel]));
            }
#pragma unroll
            for (int mi = 0; mi < 2; mi++)
#pragma unroll
                for (int ni = 0; ni < 2; ni++) {
                    mma16816(acc[mi][ni], Afh[mi], Bfh[ni]);
                    mma16816(acc[mi][ni], Afh[mi], Bfl[ni]);
                    mma16816(acc[mi][ni], Afl[mi], Bfh[ni]);
                }
        }
        __syncthreads();
    }
}

// ---------------------------------------------------------------------------
// Generic K=128 GEMM. EMODE 0 fp32 / 2 relu-split / 3 relu+sA*b split.
// z: A += z*aStr, B += z*bStr, P += z*pStr (serves both split-K and batching).
// ---------------------------------------------------------------------------
template <int EMODE>
__global__ __launch_bounds__(256) void tmm(
    const bf16* __restrict__ Ah, const bf16* __restrict__ Al, int lda, size_t aStr,
    const bf16* __restrict__ Bh, const bf16* __restrict__ Bl, int ldb, int kbOff, size_t bStr,
    const float* __restrict__ sAv, const float* __restrict__ eb,
    float* __restrict__ Pf, bf16* __restrict__ Ph, bf16* __restrict__ Pl,
    int ldp, size_t pStr)
{
    __shared__ bf16 sAh[2][64][40], sAl[2][64][40], sBh[2][64][40], sBl[2][64][40];
    int tid = threadIdx.x;
    int lane = tid & 31, wid = tid >> 5;
    int wm = (wid & 1) * 32, wn = (wid >> 1) * 16;
    int rowBase = blockIdx.x * 64, colBase = blockIdx.y * 64;
    int z = blockIdx.z;

    float acc[2][2][4] = {};
    mma_core_k128(acc, Ah + (size_t)z * aStr, Al + (size_t)z * aStr, lda,
                  Bh + (size_t)z * bStr, Bl + (size_t)z * bStr, ldb, kbOff,
                  sAh, sAl, sBh, sBl, rowBase, colBase, tid);

    int t4 = lane >> 2, t2 = (lane & 3) * 2;
#pragma unroll
    for (int mi = 0; mi < 2; mi++)
#pragma unroll
        for (int half = 0; half < 2; half++) {
            int lr = wm + mi * 16 + t4 + half * 8;
            int grow = rowBase + lr;
#pragma unroll
            for (int ni = 0; ni < 2; ni++) {
                float v0 = acc[mi][ni][half * 2 + 0];
                float v1 = acc[mi][ni][half * 2 + 1];
                int c0 = colBase + wn + ni * 8 + t2;
                if (EMODE == 0) {
                    float* po = Pf + (size_t)z * pStr + (size_t)grow * ldp;
                    po[c0] = v0; po[c0 + 1] = v1;
                } else {
                    float w0 = v0, w1 = v1;
                    if (EMODE == 3) {
                        float sa = sAv[grow];
                        w0 += sa * eb[c0]; w1 += sa * eb[c0 + 1];
                    }
                    w0 = fmaxf(w0, 0.f); w1 = fmaxf(w1, 0.f);
                    bf16* ph = Ph + (size_t)z * pStr + (size_t)grow * ldp;
                    bf16* pl = Pl + (size_t)z * pStr + (size_t)grow * ldp;
                    bf16 h, l;
                    bsplit(w0, h, l); ph[c0] = h; pl[c0] = l;
                    bsplit(w1, h, l); ph[c0 + 1] = h; pl[c0 + 1] = l;
                }
            }
        }
}

// ---------------------------------------------------------------------------
// k_dual: z=0 -> NM^T = (X@Wv + Wv_b)^T  (K=256 via two core calls)
//         z=1 -> pO[2] = relu(X)[:,0:128]   @ Wu^T[.,384:512]
//         z=2 -> pO[3] = relu(X)[:,128:256] @ Wu^T[.,512:640]
// grid (32,4,3), 256 threads.
// ---------------------------------------------------------------------------
__global__ __launch_bounds__(256) void k_dual(const float* __restrict__ Wv_b) {
    __shared__ bf16 sAh[2][64][40], sAl[2][64][40], sBh[2][64][40], sBl[2][64][40];
    int tid = threadIdx.x;
    int lane = tid & 31, wid = tid >> 5;
    int wm = (wid & 1) * 32, wn = (wid >> 1) * 16;
    int rowBase = blockIdx.x * 64, colBase = blockIdx.y * 64;
    int z = blockIdx.z;

    float acc[2][2][4] = {};
    if (z == 0) {
        mma_core_k128(acc, g_Xh, g_Xl, NH, g_WvTh, g_WvTl, NH, 0,
                      sAh, sAl, sBh, sBl, rowBase, colBase, tid);
        mma_core_k128(acc, g_Xh + 128, g_Xl + 128, NH, g_WvTh, g_WvTl, NH, 128,
                      sAh, sAl, sBh, sBl, rowBase, colBase, tid);
    } else if (z == 1) {
        mma_core_k128(acc, g_Xrh, g_Xrl, NH, g_WuTh, g_WuTl, 640, 384,
                      sAh, sAl, sBh, sBl, rowBase, colBase, tid);
    } else {
        mma_core_k128(acc, g_Xrh + 128, g_Xrl + 128, NH, g_WuTh, g_WuTl, 640, 512,
                      sAh, sAl, sBh, sBl, rowBase, colBase, tid);
    }

    int t4 = lane >> 2, t2 = (lane & 3) * 2;
#pragma unroll
    for (int mi = 0; mi < 2; mi++)
#pragma unroll
        for (int half = 0; half < 2; half++) {
            int lr = wm + mi * 16 + t4 + half * 8;
            int grow = rowBase + lr;
#pragma unroll
            for (int ni = 0; ni < 2; ni++) {
                float v0 = acc[mi][ni][half * 2 + 0];
                float v1 = acc[mi][ni][half * 2 + 1];
                int c0 = colBase + wn + ni * 8 + t2;
                if (z != 0) {
                    float* po = g_pO[z + 1] + (size_t)grow * NH;
                    po[c0] = v0; po[c0 + 1] = v1;
                } else {
                    int b = grow >> 7, ml = grow & 127;
                    bf16* ph = g_NMTh + (size_t)b * (NH * MM);
                    bf16* pl = g_NMTl + (size_t)b * (NH * MM);
                    float w0 = v0 + Wv_b[c0], w1 = v1 + Wv_b[c0 + 1];
                    bf16 h, l;
                    bsplit(w0, h, l); ph[(size_t)c0 * MM + ml] = h; pl[(size_t)c0 * MM + ml] = l;
                    bsplit(w1, h, l); ph[(size_t)(c0 + 1) * MM + ml] = h; pl[(size_t)(c0 + 1) * MM + ml] = l;
                }
            }
        }
}

// ---------------------------------------------------------------------------
__global__ __launch_bounds__(256) void k_prepX(const float* __restrict__ X) {
    int i4 = (blockIdx.x * 256 + threadIdx.x) * 4;
    float4 f = *(const float4*)(X + i4);
    bf16 h, l;
    bsplit(f.x, h, l); g_Xh[i4+0] = h; g_Xl[i4+0] = l;
    bsplit(f.y, h, l); g_Xh[i4+1] = h; g_Xl[i4+1] = l;
    bsplit(f.z, h, l); g_Xh[i4+2] = h; g_Xl[i4+2] = l;
    bsplit(f.w, h, l); g_Xh[i4+3] = h; g_Xl[i4+3] = l;
    bsplit(fmaxf(f.x, 0.f), h, l); g_Xrh[i4+0] = h; g_Xrl[i4+0] = l;
    bsplit(fmaxf(f.y, 0.f), h, l); g_Xrh[i4+1] = h; g_Xrl[i4+1] = l;
    bsplit(fmaxf(f.z, 0.f), h, l); g_Xrh[i4+2] = h; g_Xrl[i4+2] = l;
    bsplit(fmaxf(f.w, 0.f), h, l); g_Xrh[i4+3] = h; g_Xrl[i4+3] = l;
}

// ---------------------------------------------------------------------------
// k_prepT: all transpose+splits (A^T x16, Wv^T, Wu^T, We^T) in one launch.
// ---------------------------------------------------------------------------
__global__ void k_prepT(const float* __restrict__ A, const float* __restrict__ Wv,
                        const float* __restrict__ Wu, const float* __restrict__ We) {
    __shared__ float t[32][33];
    int id = blockIdx.x;
    const float* in; bf16 *Th, *Tl;
    int K, N, k0, n0;
    if (id < 256) {
        int b = id >> 4, r = id & 15;
        in = A + (size_t)b * MM * MM;
        Th = g_ATh + (size_t)b * MM * MM;
        Tl = g_ATl + (size_t)b * MM * MM;
        K = MM; N = MM; k0 = (r & 3) * 32; n0 = (r >> 2) * 32;
    } else if (id < 320) {
        int r = id - 256;
        in = Wv; Th = g_WvTh; Tl = g_WvTl;
        K = NH; N = NH; k0 = (r & 7) * 32; n0 = (r >> 3) * 32;
    } else if (id < 480) {
        int r = id - 320;
        in = Wu; Th = g_WuTh; Tl = g_WuTl;
        K = 640; N = NH; k0 = (r % 20) * 32; n0 = (r / 20) * 32;
    } else {
        int r = id - 480;
        in = We; Th = g_WeTh; Tl = g_WeTl;
        K = EH; N = EH; k0 = (r & 3) * 32; n0 = (r >> 2) * 32;
    }
    int tx = threadIdx.x, ty = threadIdx.y;
    t[ty][tx] = in[(size_t)(k0 + ty) * N + n0 + tx];
    __syncthreads();
    float v = t[tx][ty];
    bf16 h, l; bsplit(v, h, l);
    size_t o = (size_t)(n0 + ty) * K + k0 + tx;
    Th[o] = h; Tl[o] = l;
}

// ---------------------------------------------------------------------------
// Persistent E reduction -> split bf16 aggE + sA (512 CTAs grid-stride)
// ---------------------------------------------------------------------------
__global__ __launch_bounds__(256) void k_agge(const float* __restrict__ A,
                                              const float* __restrict__ E) {
    __shared__ float Ac[MM];
    __shared__ float red[8][EH];
    int t = threadIdx.x;
    int lane = t & 31, grp = t >> 5;

    for (int r = blockIdx.x; r < RR; r += gridDim.x) {
        int b = r >> 7, j = r & 127;
        if (t < MM) Ac[t] = A[(b * MM + t) * MM + j];
        __syncthreads();

        const float* Eb = E + ((size_t)b * MM * MM + j) * EH;
        float4 acc = {0.f, 0.f, 0.f, 0.f};
#pragma unroll
        for (int ii = 0; ii < MM; ii += 16) {
            int i0 = ii + grp, i1 = ii + 8 + grp;
            float4 v0 = *(const float4*)(Eb + (size_t)i0 * MM * EH + lane * 4);
            float4 v1 = *(const float4*)(Eb + (size_t)i1 * MM * EH + lane * 4);
            float a0 = Ac[i0], a1 = Ac[i1];
            acc.x += a0 * v0.x + a1 * v1.x;
            acc.y += a0 * v0.y + a1 * v1.y;
            acc.z += a0 * v0.z + a1 * v1.z;
            acc.w += a0 * v0.w + a1 * v1.w;
        }
        *(float4*)&red[grp][lane * 4] = acc;
        __syncthreads();
        if (t < EH) {
            float s = 0.f;
#pragma unroll
            for (int g = 0; g < 8; g++) s += red[g][t];
            bf16 h, l; bsplit(s, h, l);
            g_aEh[(size_t)r * EH + t] = h;
            g_aEl[(size_t)r * EH + t] = l;
        }
        if (t == 0) {
            float s = 0.f;
#pragma unroll
            for (int i = 0; i < MM; i++) s += Ac[i];
            g_sA[r] = s;
        }
        __syncthreads();
    }
}

// ---------------------------------------------------------------------------
__global__ __launch_bounds__(256) void k_final(const float* __restrict__ Wub,
                                               const float* __restrict__ w,
                                               float* __restrict__ out) {
    int r = blockIdx.x, n = threadIdx.x;
    size_t idx = (size_t)r * NH + n;
    float s = g_pO[0][idx] + g_pO[1][idx] + g_pO[2][idx] + g_pO[3][idx] + g_pO[4][idx];
    out[idx] = (s + Wub[n]) * w[r];
}

// ---------------------------------------------------------------------------
extern "C" void kernel_launch(void* const* d_in, const int* in_sizes, int n_in,
                              void* d_out, int out_size) {
    const float* X    = (const float*)d_in[0];
    const float* E    = (const float*)d_in[1];
    const float* A    = (const float*)d_in[2];
    const float* w    = (const float*)d_in[3];
    const float* Wv_w = (const float*)d_in[4];
    const float* Wv_b = (const float*)d_in[5];
    const float* We_w = (const float*)d_in[6];
    const float* We_b = (const float*)d_in[7];
    const float* Wu_w = (const float*)d_in[8];
    const float* Wu_b = (const float*)d_in[9];
    float* out = (float*)d_out;

    float *pO, *psA;
    cudaGetSymbolAddress((void**)&pO,  g_pO);
    cudaGetSymbolAddress((void**)&psA, g_sA);
    bf16 *WeTh,*WeTl,*WuTh,*WuTl,*ATh,*ATl,*NMTh,*NMTl,*hNh,*hNl,*aEh,*aEl,*hEh,*hEl;
    cudaGetSymbolAddress((void**)&WeTh,g_WeTh); cudaGetSymbolAddress((void**)&WeTl,g_WeTl);
    cudaGetSymbolAddress((void**)&WuTh,g_WuTh); cudaGetSymbolAddress((void**)&WuTl,g_WuTl);
    cudaGetSymbolAddress((void**)&ATh, g_ATh);  cudaGetSymbolAddress((void**)&ATl, g_ATl);
    cudaGetSymbolAddress((void**)&NMTh,g_NMTh); cudaGetSymbolAddress((void**)&NMTl,g_NMTl);
    cudaGetSymbolAddress((void**)&hNh, g_hNh);  cudaGetSymbolAddress((void**)&hNl, g_hNl);
    cudaGetSymbolAddress((void**)&aEh, g_aEh);  cudaGetSymbolAddress((void**)&aEl, g_aEl);
    cudaGetSymbolAddress((void**)&hEh, g_hEh);  cudaGetSymbolAddress((void**)&hEl, g_hEl);
    const size_t SL = (size_t)RR * NH;

    cudaStream_t sB, sC;
    cudaStreamCreateWithFlags(&sB, cudaStreamNonBlocking);
    cudaStreamCreateWithFlags(&sC, cudaStreamNonBlocking);
    cudaEvent_t e0, eT, eB;
    cudaEventCreateWithFlags(&e0, cudaEventDisableTiming);
    cudaEventCreateWithFlags(&eT, cudaEventDisableTiming);
    cudaEventCreateWithFlags(&eB, cudaEventDisableTiming);

    cudaEventRecord(e0, 0);
    cudaStreamWaitEvent(sB, e0, 0);
    cudaStreamWaitEvent(sC, e0, 0);

    // ---- sB: E reduction (DRAM-bound, starts immediately) ----
    k_agge<<<512, 256, 0, sB>>>(A, E);

    // ---- sC: all transposes+splits in one kernel ----
    k_prepT<<<496, dim3(32, 32), 0, sC>>>(A, Wv_w, Wu_w, We_w);
    cudaEventRecord(eT, sC);

    // ---- s0: X split -> dual GEMM -> node chain ----
    k_prepX<<<512, 256>>>(X);
    cudaStreamWaitEvent(0, eT, 0);
    // z0: NM^T (K=256); z1,z2: relu(X)@Wu[384:640] halves -> pO[2],pO[3]
    k_dual<<<dim3(32, 4, 3), 256>>>(Wv_b);
    // hN = relu(A^T @ NM) per batch (z = batch)
    tmm<2><<<dim3(2, 4, 16), 256>>>(
        ATh, ATl, MM, (size_t)MM * MM, NMTh, NMTl, MM, 0, (size_t)NH * MM,
        nullptr, nullptr, nullptr, hNh, hNl, NH, (size_t)MM * NH);
    // pO[0],pO[1] = hN @ Wu[0:256] (split-K via z: aStr/bStr = 128)
    tmm<0><<<dim3(32, 4, 2), 256>>>(
        hNh, hNl, NH, 128, WuTh, WuTl, 640, 0, 128,
        nullptr, nullptr, pO, nullptr, nullptr, NH, SL);

    // ---- sB: edge chain ----
    cudaStreamWaitEvent(sB, eT, 0);
    // hE = relu(aggE @ We + sA*We_b)
    tmm<3><<<dim3(32, 2, 1), 256, 0, sB>>>(
        aEh, aEl, EH, 0, WeTh, WeTl, EH, 0, 0,
        psA, We_b, nullptr, hEh, hEl, EH, 0);
    // pO[4] = hE @ Wu[256:384]
    tmm<0><<<dim3(32, 4, 1), 256, 0, sB>>>(
        hEh, hEl, EH, 0, WuTh, WuTl, 640, 256, 0,
        nullptr, nullptr, pO + 4 * SL, nullptr, nullptr, NH, 0);
    cudaEventRecord(eB, sB);

    // ---- join ----
    cudaStreamWaitEvent(0, eB, 0);
    k_final<<<RR, 256>>>(Wu_b, w, out);

    cudaEventDestroy(e0); cudaEventDestroy(eT); cudaEventDestroy(eB);
    cudaStreamDestroy(sB); cudaStreamDestroy(sC);
}